// round 10
// baseline (speedup 1.0000x reference)
#include <cuda_runtime.h>
#include <math.h>

#define NMAX 50000
#define EMAX 600000
#define HDIM 128
#define NHEADS 4
#define GMAX 64

// ---------------- scratch (device globals; no allocation) ----------------
__device__ float d_h[NMAX * HDIM];
__device__ float d_feat[NMAX * HDIM];
__device__ float d_el[NMAX * NHEADS];
__device__ float d_er[NMAX * NHEADS];
__device__ float d_elmax[3 * NHEADS];
__device__ int   d_deg[NMAX];
__device__ int   d_offs[NMAX + 1];
__device__ int   d_esrc[EMAX];
__device__ int   d_bsum[64];
__device__ int   d_bbase[64];
__device__ float d_gz[GMAX];
__device__ float d_zg[GMAX * HDIM];

// ---------------- helpers ----------------
__device__ __forceinline__ void atomicMaxFloat(float* addr, float v) {
    if (v >= 0.0f) atomicMax((int*)addr, __float_as_int(v));
    else           atomicMin((unsigned int*)addr, __float_as_uint(v));
}

__device__ __forceinline__ void redAdd4(float* p, float a, float b, float c, float d) {
    asm volatile("red.global.add.v4.f32 [%0], {%1, %2, %3, %4};"
                 :: "l"(p), "f"(a), "f"(b), "f"(c), "f"(d) : "memory");
}

__device__ __forceinline__ float warpSum(float v) {
    #pragma unroll
    for (int o = 16; o > 0; o >>= 1) v += __shfl_xor_sync(0xffffffffu, v, o);
    return v;
}

// packed fp32x2 FMA (Blackwell)
#define FMA2(d, a, b) asm("fma.rn.f32x2 %0, %1, %2, %0;" : "+l"(d) : "l"(a), "l"(b))
#define PACK_DUP(d, x) asm("mov.b64 %0, {%1, %1};" : "=l"(d) : "r"(__float_as_uint(x)))
#define UNPACK2(lo, hi, v) asm("mov.b64 {%0, %1}, %2;" : "=r"(lo), "=r"(hi) : "l"(v))

// ---------------- kernels ----------------

// --------- CSR build + global init (once per call) ---------
__global__ void csr_zero_k(int n) {
    int i = blockIdx.x * blockDim.x + threadIdx.x;
    if (i < n) d_deg[i] = 0;
    if (i < 3 * NHEADS) d_elmax[i] = -1e30f;
    if (i < GMAX * HDIM) d_zg[i] = 0.0f;
    if (i < GMAX) d_gz[i] = 0.0f;
}

__global__ void csr_hist_k(const int* __restrict__ dst, int e) {
    int i = blockIdx.x * blockDim.x + threadIdx.x;
    if (i < e) atomicAdd(&d_deg[dst[i]], 1);
}

__global__ void csr_scan1_k(int n) {
    __shared__ int wsum[32];
    int i = blockIdx.x * 1024 + threadIdx.x;
    int lane = threadIdx.x & 31, wid = threadIdx.x >> 5;
    int v = (i < n) ? d_deg[i] : 0;
    int x = v;
    #pragma unroll
    for (int o = 1; o < 32; o <<= 1) {
        int t = __shfl_up_sync(0xffffffffu, x, o);
        if (lane >= o) x += t;
    }
    if (lane == 31) wsum[wid] = x;
    __syncthreads();
    if (wid == 0) {
        int y = wsum[lane];
        #pragma unroll
        for (int o = 1; o < 32; o <<= 1) {
            int t = __shfl_up_sync(0xffffffffu, y, o);
            if (lane >= o) y += t;
        }
        wsum[lane] = y;
    }
    __syncthreads();
    int base = (wid > 0) ? wsum[wid - 1] : 0;
    if (i < n) d_offs[i] = base + x - v;
    if (threadIdx.x == 1023) d_bsum[blockIdx.x] = wsum[31];
}

__global__ void csr_scan2_k(int nb, int n) {
    int lane = threadIdx.x;
    int v0 = (lane < nb) ? d_bsum[lane] : 0;
    int v1 = (32 + lane < nb) ? d_bsum[32 + lane] : 0;
    int x0 = v0, x1 = v1;
    #pragma unroll
    for (int o = 1; o < 32; o <<= 1) {
        int t0 = __shfl_up_sync(0xffffffffu, x0, o);
        int t1 = __shfl_up_sync(0xffffffffu, x1, o);
        if (lane >= o) { x0 += t0; x1 += t1; }
    }
    int tot0 = __shfl_sync(0xffffffffu, x0, 31);
    int tot1 = __shfl_sync(0xffffffffu, x1, 31);
    if (lane < nb) d_bbase[lane] = x0 - v0;
    if (32 + lane < nb) d_bbase[32 + lane] = tot0 + x1 - v1;
    if (lane == 0) d_offs[n] = tot0 + tot1;
}

__global__ void csr_scan3_k(int n) {
    int i = blockIdx.x * 1024 + threadIdx.x;
    if (i < n) d_offs[i] += d_bbase[blockIdx.x];
}

// Destructive scatter: after this, d_offs[i] == CSR start of node i+1
// (i.e. exclusive prefix INCLUDING node i). gat_fused reads the shifted form.
__global__ void csr_scatter_k(const int* __restrict__ src, const int* __restrict__ dst, int e) {
    int i = blockIdx.x * blockDim.x + threadIdx.x;
    if (i >= e) return;
    int d = dst[i];
    int pos = atomicAdd(&d_offs[d], 1);
    d_esrc[pos] = src[i];
}

// feat = h @ W[l] with fused attn epilogue + per-head global el-max.
// For l==0 (gt != nullptr) the embedding h = ge[gt]+qe[qi] is computed in the
// staging loop and also written to d_h.
__global__ void __launch_bounds__(256, 4)
gemm_attn_k(const float* __restrict__ B,
            const float* __restrict__ al, const float* __restrict__ ar,
            int n, int l,
            const int* __restrict__ gt, const int* __restrict__ qi,
            const float* __restrict__ ge, const float* __restrict__ qe) {
    __shared__ float Ast[HDIM][68];
    __shared__ float smax[NHEADS];
    int row0 = blockIdx.x * 64;
    int tid = threadIdx.x;
    if (tid < NHEADS) smax[tid] = -1e30f;
    #pragma unroll
    for (int it = 0; it < 8; it++) {
        int idx4 = tid + it * 256;
        int r = idx4 >> 5;                     // 0..63
        int c = (idx4 & 31) * 4;               // 0..124
        int row = row0 + r;
        float4 v = make_float4(0.f, 0.f, 0.f, 0.f);
        if (row < n) {
            if (gt) {
                int gg = gt[row], qq = qi[row];
                float4 a = *(const float4*)(ge + gg * HDIM + c);
                float4 b = *(const float4*)(qe + qq * HDIM + c);
                v.x = a.x + b.x; v.y = a.y + b.y; v.z = a.z + b.z; v.w = a.w + b.w;
                *(float4*)(d_h + row * HDIM + c) = v;
            } else {
                v = *(const float4*)(d_h + row * HDIM + c);
            }
        }
        Ast[c][r] = v.x; Ast[c + 1][r] = v.y; Ast[c + 2][r] = v.z; Ast[c + 3][r] = v.w;
    }
    __syncthreads();
    int wid = tid >> 5, lane = tid & 31;
    int rbase = wid * 8;
    int col = lane * 4;
    int head = lane >> 3;

    unsigned long long acc2[4][4];
    #pragma unroll
    for (int rp = 0; rp < 4; rp++)
        #pragma unroll
        for (int c = 0; c < 4; c++) acc2[rp][c] = 0ull;

    #pragma unroll 8
    for (int k = 0; k < HDIM; k++) {
        unsigned long long ap[4];
        #pragma unroll
        for (int rp = 0; rp < 4; rp++)
            ap[rp] = *(const unsigned long long*)&Ast[k][rbase + 2 * rp];
        float4 b = __ldg((const float4*)(B + k * HDIM + col));
        unsigned long long bd[4];
        PACK_DUP(bd[0], b.x); PACK_DUP(bd[1], b.y);
        PACK_DUP(bd[2], b.z); PACK_DUP(bd[3], b.w);
        #pragma unroll
        for (int rp = 0; rp < 4; rp++) {
            FMA2(acc2[rp][0], ap[rp], bd[0]);
            FMA2(acc2[rp][1], ap[rp], bd[1]);
            FMA2(acc2[rp][2], ap[rp], bd[2]);
            FMA2(acc2[rp][3], ap[rp], bd[3]);
        }
    }

    float acc[8][4];
    #pragma unroll
    for (int rp = 0; rp < 4; rp++)
        #pragma unroll
        for (int c = 0; c < 4; c++) {
            unsigned int lo, hi;
            UNPACK2(lo, hi, acc2[rp][c]);
            acc[2 * rp][c] = __uint_as_float(lo);
            acc[2 * rp + 1][c] = __uint_as_float(hi);
        }

    float4 av = __ldg((const float4*)(al + col));
    float4 rv = __ldg((const float4*)(ar + col));
    float myelmax = -1e30f;
    #pragma unroll
    for (int r = 0; r < 8; r++) {
        int row = row0 + rbase + r;
        if (row < n) {
            float4 o = make_float4(acc[r][0], acc[r][1], acc[r][2], acc[r][3]);
            *(float4*)(d_feat + row * HDIM + col) = o;
        }
        float sl = acc[r][0] * av.x + acc[r][1] * av.y + acc[r][2] * av.z + acc[r][3] * av.w;
        float sr = acc[r][0] * rv.x + acc[r][1] * rv.y + acc[r][2] * rv.z + acc[r][3] * rv.w;
        #pragma unroll
        for (int o = 4; o > 0; o >>= 1) {
            sl += __shfl_xor_sync(0xffffffffu, sl, o);
            sr += __shfl_xor_sync(0xffffffffu, sr, o);
        }
        if ((lane & 7) == 0 && row < n) {
            d_el[row * NHEADS + head] = sl;
            d_er[row * NHEADS + head] = sr;
            myelmax = fmaxf(myelmax, sl);
        }
    }
    if ((lane & 7) == 0) atomicMaxFloat(&smax[head], myelmax);
    __syncthreads();
    if (tid < NHEADS) atomicMaxFloat(&d_elmax[l * NHEADS + tid], smax[tid]);
}

// Fused per-layer GAT aggregation: warp per dst node. Single edge pass; free z.
// Uses SHIFTED offsets (post-destructive-scatter): rs = offs[node-1] (0 for 0),
// re = offs[node].
__global__ void gat_fused_k(const float* __restrict__ bias, int n, int l) {
    __shared__ float sh_a[8][128];
    int warp = (blockIdx.x * blockDim.x + threadIdx.x) >> 5;
    if (warp >= n) return;
    int w = threadIdx.x >> 5;
    int lane = threadIdx.x & 31;
    int node = warp;
    int rs = (node > 0) ? d_offs[node - 1] : 0;
    int re = d_offs[node];
    int head = lane >> 3;

    float4 er4 = *(const float4*)(d_er + node * NHEADS);
    float4 em = *(const float4*)(d_elmax + l * NHEADS);
    float m[4];
    {
        float t0 = em.x + er4.x; m[0] = (t0 > 0.0f) ? t0 : 0.2f * t0;
        float t1 = em.y + er4.y; m[1] = (t1 > 0.0f) ? t1 : 0.2f * t1;
        float t2 = em.z + er4.z; m[2] = (t2 > 0.0f) ? t2 : 0.2f * t2;
        float t3 = em.w + er4.w; m[3] = (t3 > 0.0f) ? t3 : 0.2f * t3;
    }

    float z = 0.0f;
    float4 acc = make_float4(0.0f, 0.0f, 0.0f, 0.0f);
    for (int base = rs; base < re; base += 32) {
        int i = base + lane;
        int s_reg = 0;
        float4 a4 = make_float4(0.0f, 0.0f, 0.0f, 0.0f);
        if (i < re) {
            s_reg = d_esrc[i];
            float4 el4 = *(const float4*)(d_el + s_reg * NHEADS);
            float v0 = el4.x + er4.x; v0 = (v0 > 0.0f) ? v0 : 0.2f * v0;
            float v1 = el4.y + er4.y; v1 = (v1 > 0.0f) ? v1 : 0.2f * v1;
            float v2 = el4.z + er4.z; v2 = (v2 > 0.0f) ? v2 : 0.2f * v2;
            float v3 = el4.w + er4.w; v3 = (v3 > 0.0f) ? v3 : 0.2f * v3;
            a4.x = __expf(v0 - m[0]); a4.y = __expf(v1 - m[1]);
            a4.z = __expf(v2 - m[2]); a4.w = __expf(v3 - m[3]);
        }
        *(float4*)&sh_a[w][lane * 4] = a4;
        __syncwarp();
        int cnt = min(32, re - base);
        #pragma unroll 4
        for (int j = 0; j < cnt; j++) {
            int s = __shfl_sync(0xffffffffu, s_reg, j);
            float a = sh_a[w][j * 4 + head];
            z += a;
            float4 f = *(const float4*)(d_feat + s * HDIM + lane * 4);
            acc.x += a * f.x; acc.y += a * f.y; acc.z += a * f.z; acc.w += a * f.w;
        }
        __syncwarp();
    }
    float rz = (z > 0.0f) ? (1.0f / z) : 0.0f;

    float4 hv = *(const float4*)(d_h + node * HDIM + lane * 4);
    float4 bv = *(const float4*)(bias + lane * 4);
    float4 y;
    y.x = fmaxf(acc.x * rz + hv.x + bv.x, 0.0f);
    y.y = fmaxf(acc.y * rz + hv.y + bv.y, 0.0f);
    y.z = fmaxf(acc.z * rz + hv.z + bv.z, 0.0f);
    y.w = fmaxf(acc.w * rz + hv.w + bv.w, 0.0f);
    *(float4*)(d_h + node * HDIM + lane * 4) = y;
}

// Fused LayerNorm + gate + pooling accumulation (shift-0 exp: LN bounds gate).
__global__ void ln_gate_pool_k(const float* __restrict__ gamma, const float* __restrict__ beta,
                               const float* __restrict__ gw, const float* __restrict__ gb,
                               const int* __restrict__ gid, int n) {
    int t = blockIdx.x * blockDim.x + threadIdx.x;
    int node = t >> 5;
    if (node >= n) return;
    int lane = t & 31;
    float4 x = *(const float4*)(d_h + node * HDIM + lane * 4);
    float s = x.x + x.y + x.z + x.w;
    float sq = x.x * x.x + x.y * x.y + x.z * x.z + x.w * x.w;
    s = warpSum(s);
    sq = warpSum(sq);
    float mu = s * (1.0f / HDIM);
    float var = sq * (1.0f / HDIM) - mu * mu;
    float inv = rsqrtf(var + 1e-5f);
    float4 g = *(const float4*)(gamma + lane * 4);
    float4 b = *(const float4*)(beta + lane * 4);
    float4 y;
    y.x = (x.x - mu) * inv * g.x + b.x;
    y.y = (x.y - mu) * inv * g.y + b.y;
    y.z = (x.z - mu) * inv * g.z + b.z;
    y.w = (x.w - mu) * inv * g.w + b.w;
    float4 w = *(const float4*)(gw + lane * 4);
    float gp = y.x * w.x + y.y * w.y + y.z * w.z + y.w * w.w;
    gp = warpSum(gp);
    float p = __expf(gp + gb[0]);
    int gr = gid[node];
    if (lane == 0) atomicAdd(&d_gz[gr], p);
    redAdd4(d_zg + gr * HDIM + lane * 4, p * y.x, p * y.y, p * y.z, p * y.w);
}

// out = relu((zg/gz) @ W1 + b1) @ W2 + b2, one block per graph
__global__ void final_k(const float* __restrict__ W1, const float* __restrict__ b1,
                        const float* __restrict__ W2, const float* __restrict__ b2,
                        float* __restrict__ out) {
    __shared__ float row[HDIM];
    __shared__ float z1[HDIM];
    int g = blockIdx.x;
    int t = threadIdx.x;
    float gz = d_gz[g];
    float inv = (gz > 0.0f) ? (1.0f / gz) : 0.0f;
    row[t] = d_zg[g * HDIM + t] * inv;
    __syncthreads();
    float acc = b1[t];
    #pragma unroll 8
    for (int k = 0; k < HDIM; k++) acc += row[k] * W1[k * HDIM + t];
    z1[t] = (acc > 0.0f) ? acc : 0.0f;
    __syncthreads();
    if (t < 64) {
        float a2 = b2[t];
        #pragma unroll 8
        for (int k = 0; k < HDIM; k++) a2 += z1[k] * W2[k * 64 + t];
        out[g * 64 + t] = a2;
    }
}

// ---------------- launch ----------------
extern "C" void kernel_launch(void* const* d_in, const int* in_sizes, int n_in,
                              void* d_out, int out_size) {
    const int*   gt    = (const int*)d_in[0];
    const int*   qi    = (const int*)d_in[1];
    const int*   src   = (const int*)d_in[2];
    const int*   dst   = (const int*)d_in[3];
    const int*   gid   = (const int*)d_in[4];
    const float* ge    = (const float*)d_in[5];
    const float* qe    = (const float*)d_in[6];
    const float* W     = (const float*)d_in[7];
    const float* al    = (const float*)d_in[8];
    const float* ar    = (const float*)d_in[9];
    const float* bias  = (const float*)d_in[10];
    const float* gamma = (const float*)d_in[11];
    const float* beta  = (const float*)d_in[12];
    const float* gw    = (const float*)d_in[13];
    const float* gb    = (const float*)d_in[14];
    const float* W1    = (const float*)d_in[15];
    const float* b1    = (const float*)d_in[16];
    const float* W2    = (const float*)d_in[17];
    const float* b2    = (const float*)d_in[18];

    int n = in_sizes[0];
    int e = in_sizes[2];

    const int T = 256;
    int gGemm  = (n + 63) / 64;
    int gWarpN = (n * 32 + T - 1) / T;
    int gEdge  = (e + T - 1) / T;
    int gNode  = (n + T - 1) / T;
    int nb     = (n + 1023) / 1024;

    csr_zero_k<<<gNode, T>>>(n);                                   // 1
    csr_hist_k<<<gEdge, T>>>(dst, e);                              // 2
    csr_scan1_k<<<nb, 1024>>>(n);                                  // 3
    gemm_attn_k<<<gGemm, 256>>>(W, al, ar, n, 0, gt, qi, ge, qe);  // 4 (profiled)
    csr_scan2_k<<<1, 32>>>(nb, n);                                 // 5
    csr_scan3_k<<<nb, 1024>>>(n);                                  // 6
    csr_scatter_k<<<gEdge, T>>>(src, dst, e);                      // 7
    gat_fused_k<<<gWarpN, T>>>(bias, n, 0);                        // 8

    for (int l = 1; l < 3; l++) {
        gemm_attn_k<<<gGemm, 256>>>(W + l * HDIM * HDIM, al + l * HDIM, ar + l * HDIM,
                                    n, l, nullptr, nullptr, nullptr, nullptr);
        gat_fused_k<<<gWarpN, T>>>(bias + l * HDIM, n, l);
    }

    ln_gate_pool_k<<<gWarpN, T>>>(gamma, beta, gw, gb, gid, n);
    final_k<<<GMAX, HDIM>>>(W1, b1, W2, b2, (float*)d_out);
}

// round 11
// speedup vs baseline: 1.0330x; 1.0330x over previous
#include <cuda_runtime.h>
#include <math.h>

#define NMAX 50000
#define EMAX 600000
#define HDIM 128
#define NHEADS 4
#define GMAX 64

// ---------------- scratch (device globals; no allocation) ----------------
__device__ float d_h[NMAX * HDIM];
__device__ float d_feat[NMAX * HDIM];
__device__ float d_el[NMAX * NHEADS];
__device__ float d_er[NMAX * NHEADS];
__device__ float d_elmax[3 * NHEADS];
__device__ int   d_deg[NMAX];
__device__ int   d_offs[NMAX + 1];
__device__ int   d_esrc[EMAX];
__device__ int   d_bsum[64];
__device__ int   d_bbase[64];
__device__ float d_gz[GMAX];
__device__ float d_zg[GMAX * HDIM];

// ---------------- helpers ----------------
__device__ __forceinline__ void atomicMaxFloat(float* addr, float v) {
    if (v >= 0.0f) atomicMax((int*)addr, __float_as_int(v));
    else           atomicMin((unsigned int*)addr, __float_as_uint(v));
}

__device__ __forceinline__ void redAdd4(float* p, float a, float b, float c, float d) {
    asm volatile("red.global.add.v4.f32 [%0], {%1, %2, %3, %4};"
                 :: "l"(p), "f"(a), "f"(b), "f"(c), "f"(d) : "memory");
}

__device__ __forceinline__ float warpSum(float v) {
    #pragma unroll
    for (int o = 16; o > 0; o >>= 1) v += __shfl_xor_sync(0xffffffffu, v, o);
    return v;
}

// packed fp32x2 FMA (Blackwell)
#define FMA2(d, a, b) asm("fma.rn.f32x2 %0, %1, %2, %0;" : "+l"(d) : "l"(a), "l"(b))
#define PACK_DUP(d, x) asm("mov.b64 %0, {%1, %1};" : "=l"(d) : "r"(__float_as_uint(x)))
#define UNPACK2(lo, hi, v) asm("mov.b64 {%0, %1}, %2;" : "=r"(lo), "=r"(hi) : "l"(v))

// ---------------- kernels ----------------

// --------- CSR build + global init (once per call) ---------
__global__ void csr_zero_k(int n) {
    int i = blockIdx.x * blockDim.x + threadIdx.x;
    if (i < n) d_deg[i] = 0;
    if (i < 3 * NHEADS) d_elmax[i] = -1e30f;
    if (i < GMAX * HDIM) d_zg[i] = 0.0f;
    if (i < GMAX) d_gz[i] = 0.0f;
}

__global__ void csr_hist_k(const int* __restrict__ dst, int e) {
    int i = blockIdx.x * blockDim.x + threadIdx.x;
    if (i < e) atomicAdd(&d_deg[dst[i]], 1);
}

__global__ void csr_scan1_k(int n) {
    __shared__ int wsum[32];
    int i = blockIdx.x * 1024 + threadIdx.x;
    int lane = threadIdx.x & 31, wid = threadIdx.x >> 5;
    int v = (i < n) ? d_deg[i] : 0;
    int x = v;
    #pragma unroll
    for (int o = 1; o < 32; o <<= 1) {
        int t = __shfl_up_sync(0xffffffffu, x, o);
        if (lane >= o) x += t;
    }
    if (lane == 31) wsum[wid] = x;
    __syncthreads();
    if (wid == 0) {
        int y = wsum[lane];
        #pragma unroll
        for (int o = 1; o < 32; o <<= 1) {
            int t = __shfl_up_sync(0xffffffffu, y, o);
            if (lane >= o) y += t;
        }
        wsum[lane] = y;
    }
    __syncthreads();
    int base = (wid > 0) ? wsum[wid - 1] : 0;
    if (i < n) d_offs[i] = base + x - v;
    if (threadIdx.x == 1023) d_bsum[blockIdx.x] = wsum[31];
}

__global__ void csr_scan2_k(int nb, int n) {
    int lane = threadIdx.x;
    int v0 = (lane < nb) ? d_bsum[lane] : 0;
    int v1 = (32 + lane < nb) ? d_bsum[32 + lane] : 0;
    int x0 = v0, x1 = v1;
    #pragma unroll
    for (int o = 1; o < 32; o <<= 1) {
        int t0 = __shfl_up_sync(0xffffffffu, x0, o);
        int t1 = __shfl_up_sync(0xffffffffu, x1, o);
        if (lane >= o) { x0 += t0; x1 += t1; }
    }
    int tot0 = __shfl_sync(0xffffffffu, x0, 31);
    int tot1 = __shfl_sync(0xffffffffu, x1, 31);
    if (lane < nb) d_bbase[lane] = x0 - v0;
    if (32 + lane < nb) d_bbase[32 + lane] = tot0 + x1 - v1;
    if (lane == 0) d_offs[n] = tot0 + tot1;
}

__global__ void csr_scan3_k(int n) {
    int i = blockIdx.x * 1024 + threadIdx.x;
    if (i < n) d_offs[i] += d_bbase[blockIdx.x];
}

// Destructive scatter: after this, d_offs[i] == end of node i's edge range.
__global__ void csr_scatter_k(const int* __restrict__ src, const int* __restrict__ dst, int e) {
    int i = blockIdx.x * blockDim.x + threadIdx.x;
    if (i >= e) return;
    int d = dst[i];
    int pos = atomicAdd(&d_offs[d], 1);
    d_esrc[pos] = src[i];
}

// feat = h @ W[l], register-blocked SGEMM: 128x128 block, 256 threads,
// 8x8 micro-tile per thread, k-chunks of 8 staged in shared.
// Fused attn epilogue (el/er + global el-max). l==0: embed pre-phase.
__global__ void __launch_bounds__(256, 2)
gemm_attn_k(const float* __restrict__ B,
            const float* __restrict__ al, const float* __restrict__ ar,
            int n, int l,
            const int* __restrict__ gt, const int* __restrict__ qi,
            const float* __restrict__ ge, const float* __restrict__ qe) {
    __shared__ float A_sh[8][132];   // [k][row], padded
    __shared__ float B_sh[8][128];   // [k][col]
    __shared__ float smax[NHEADS];
    int row0 = blockIdx.x * 128;
    int tid = threadIdx.x;
    int tx = tid & 15;               // col group: cols tx*8..+7
    int ty = tid >> 4;               // row group: rows ty*8..+7
    if (tid < NHEADS) smax[tid] = -1e30f;

    // l==0: compute embedding for this block's rows into d_h
    if (gt) {
        #pragma unroll
        for (int it = 0; it < 16; it++) {
            int idx4 = tid + it * 256;
            int row = row0 + (idx4 >> 5);
            int c = (idx4 & 31) * 4;
            if (row < n) {
                int gg = gt[row], qq = qi[row];
                float4 a = *(const float4*)(ge + gg * HDIM + c);
                float4 b = *(const float4*)(qe + qq * HDIM + c);
                float4 v;
                v.x = a.x + b.x; v.y = a.y + b.y; v.z = a.z + b.z; v.w = a.w + b.w;
                *(float4*)(d_h + row * HDIM + c) = v;
            }
        }
        __syncthreads();
    }

    unsigned long long acc2[4][8];   // row-pairs x 8 cols
    #pragma unroll
    for (int rp = 0; rp < 4; rp++)
        #pragma unroll
        for (int c = 0; c < 8; c++) acc2[rp][c] = 0ull;

    // staging indices
    int sa_row = tid >> 1;            // 0..127
    int sa_kp = (tid & 1) * 4;        // 0 or 4
    int sb_kr = tid >> 5;             // 0..7
    int sb_c = (tid & 31) * 4;        // 0..124

    for (int kc = 0; kc < HDIM; kc += 8) {
        // stage A (128 rows x 8 k, transposed) and B (8 k x 128 cols)
        float4 va = make_float4(0.f, 0.f, 0.f, 0.f);
        if (row0 + sa_row < n)
            va = *(const float4*)(d_h + (row0 + sa_row) * HDIM + kc + sa_kp);
        A_sh[sa_kp + 0][sa_row] = va.x;
        A_sh[sa_kp + 1][sa_row] = va.y;
        A_sh[sa_kp + 2][sa_row] = va.z;
        A_sh[sa_kp + 3][sa_row] = va.w;
        *(float4*)&B_sh[sb_kr][sb_c] = __ldg((const float4*)(B + (kc + sb_kr) * HDIM + sb_c));
        __syncthreads();

        #pragma unroll
        for (int k = 0; k < 8; k++) {
            float4 af[2];
            const float4* arow = (const float4*)&A_sh[k][ty * 8];
            af[0] = arow[0]; af[1] = arow[1];
            const float4* brow = (const float4*)&B_sh[k][tx * 8];
            float4 b0 = brow[0], b1 = brow[1];
            unsigned long long bd[8];
            PACK_DUP(bd[0], b0.x); PACK_DUP(bd[1], b0.y);
            PACK_DUP(bd[2], b0.z); PACK_DUP(bd[3], b0.w);
            PACK_DUP(bd[4], b1.x); PACK_DUP(bd[5], b1.y);
            PACK_DUP(bd[6], b1.z); PACK_DUP(bd[7], b1.w);
            const unsigned long long* ap = (const unsigned long long*)af;
            #pragma unroll
            for (int rp = 0; rp < 4; rp++) {
                #pragma unroll
                for (int c = 0; c < 8; c++)
                    FMA2(acc2[rp][c], ap[rp], bd[c]);
            }
        }
        __syncthreads();
    }

    // unpack
    float acc[8][8];
    #pragma unroll
    for (int rp = 0; rp < 4; rp++)
        #pragma unroll
        for (int c = 0; c < 8; c++) {
            unsigned int lo, hi;
            UNPACK2(lo, hi, acc2[rp][c]);
            acc[2 * rp][c] = __uint_as_float(lo);
            acc[2 * rp + 1][c] = __uint_as_float(hi);
        }

    // epilogue: store feat + el/er + elmax
    float4 av0 = __ldg((const float4*)(al + tx * 8));
    float4 av1 = __ldg((const float4*)(al + tx * 8 + 4));
    float4 rv0 = __ldg((const float4*)(ar + tx * 8));
    float4 rv1 = __ldg((const float4*)(ar + tx * 8 + 4));
    int head = tx >> 2;
    float myelmax = -1e30f;
    #pragma unroll
    for (int r = 0; r < 8; r++) {
        int row = row0 + ty * 8 + r;
        if (row < n) {
            *(float4*)(d_feat + row * HDIM + tx * 8) =
                make_float4(acc[r][0], acc[r][1], acc[r][2], acc[r][3]);
            *(float4*)(d_feat + row * HDIM + tx * 8 + 4) =
                make_float4(acc[r][4], acc[r][5], acc[r][6], acc[r][7]);
        }
        float sl = acc[r][0] * av0.x + acc[r][1] * av0.y + acc[r][2] * av0.z + acc[r][3] * av0.w
                 + acc[r][4] * av1.x + acc[r][5] * av1.y + acc[r][6] * av1.z + acc[r][7] * av1.w;
        float sr = acc[r][0] * rv0.x + acc[r][1] * rv0.y + acc[r][2] * rv0.z + acc[r][3] * rv0.w
                 + acc[r][4] * rv1.x + acc[r][5] * rv1.y + acc[r][6] * rv1.z + acc[r][7] * rv1.w;
        sl += __shfl_xor_sync(0xffffffffu, sl, 1);
        sl += __shfl_xor_sync(0xffffffffu, sl, 2);
        sr += __shfl_xor_sync(0xffffffffu, sr, 1);
        sr += __shfl_xor_sync(0xffffffffu, sr, 2);
        if ((tx & 3) == 0 && row < n) {
            d_el[row * NHEADS + head] = sl;
            d_er[row * NHEADS + head] = sr;
            myelmax = fmaxf(myelmax, sl);
        }
    }
    if ((tx & 3) == 0) atomicMaxFloat(&smax[head], myelmax);
    __syncthreads();
    if (tid < NHEADS) atomicMaxFloat(&d_elmax[l * NHEADS + tid], smax[tid]);
}

// Fused per-layer GAT aggregation: warp per dst node. Single edge pass; free z.
// Shifted offsets (post-destructive-scatter): rs = offs[node-1] (0 for 0), re = offs[node].
__global__ void gat_fused_k(const float* __restrict__ bias, int n, int l) {
    __shared__ float sh_a[8][128];
    int warp = (blockIdx.x * blockDim.x + threadIdx.x) >> 5;
    if (warp >= n) return;
    int w = threadIdx.x >> 5;
    int lane = threadIdx.x & 31;
    int node = warp;
    int rs = (node > 0) ? d_offs[node - 1] : 0;
    int re = d_offs[node];
    int head = lane >> 3;

    float4 er4 = *(const float4*)(d_er + node * NHEADS);
    float4 em = *(const float4*)(d_elmax + l * NHEADS);
    float m[4];
    {
        float t0 = em.x + er4.x; m[0] = (t0 > 0.0f) ? t0 : 0.2f * t0;
        float t1 = em.y + er4.y; m[1] = (t1 > 0.0f) ? t1 : 0.2f * t1;
        float t2 = em.z + er4.z; m[2] = (t2 > 0.0f) ? t2 : 0.2f * t2;
        float t3 = em.w + er4.w; m[3] = (t3 > 0.0f) ? t3 : 0.2f * t3;
    }

    float z = 0.0f;
    float4 acc = make_float4(0.0f, 0.0f, 0.0f, 0.0f);
    for (int base = rs; base < re; base += 32) {
        int i = base + lane;
        int s_reg = 0;
        float4 a4 = make_float4(0.0f, 0.0f, 0.0f, 0.0f);
        if (i < re) {
            s_reg = d_esrc[i];
            float4 el4 = *(const float4*)(d_el + s_reg * NHEADS);
            float v0 = el4.x + er4.x; v0 = (v0 > 0.0f) ? v0 : 0.2f * v0;
            float v1 = el4.y + er4.y; v1 = (v1 > 0.0f) ? v1 : 0.2f * v1;
            float v2 = el4.z + er4.z; v2 = (v2 > 0.0f) ? v2 : 0.2f * v2;
            float v3 = el4.w + er4.w; v3 = (v3 > 0.0f) ? v3 : 0.2f * v3;
            a4.x = __expf(v0 - m[0]); a4.y = __expf(v1 - m[1]);
            a4.z = __expf(v2 - m[2]); a4.w = __expf(v3 - m[3]);
        }
        *(float4*)&sh_a[w][lane * 4] = a4;
        __syncwarp();
        int cnt = min(32, re - base);
        #pragma unroll 4
        for (int j = 0; j < cnt; j++) {
            int s = __shfl_sync(0xffffffffu, s_reg, j);
            float a = sh_a[w][j * 4 + head];
            z += a;
            float4 f = *(const float4*)(d_feat + s * HDIM + lane * 4);
            acc.x += a * f.x; acc.y += a * f.y; acc.z += a * f.z; acc.w += a * f.w;
        }
        __syncwarp();
    }
    float rz = (z > 0.0f) ? (1.0f / z) : 0.0f;

    float4 hv = *(const float4*)(d_h + node * HDIM + lane * 4);
    float4 bv = *(const float4*)(bias + lane * 4);
    float4 y;
    y.x = fmaxf(acc.x * rz + hv.x + bv.x, 0.0f);
    y.y = fmaxf(acc.y * rz + hv.y + bv.y, 0.0f);
    y.z = fmaxf(acc.z * rz + hv.z + bv.z, 0.0f);
    y.w = fmaxf(acc.w * rz + hv.w + bv.w, 0.0f);
    *(float4*)(d_h + node * HDIM + lane * 4) = y;
}

// Fused LayerNorm + gate + pooling accumulation (shift-0 exp: LN bounds gate).
__global__ void ln_gate_pool_k(const float* __restrict__ gamma, const float* __restrict__ beta,
                               const float* __restrict__ gw, const float* __restrict__ gb,
                               const int* __restrict__ gid, int n) {
    int t = blockIdx.x * blockDim.x + threadIdx.x;
    int node = t >> 5;
    if (node >= n) return;
    int lane = t & 31;
    float4 x = *(const float4*)(d_h + node * HDIM + lane * 4);
    float s = x.x + x.y + x.z + x.w;
    float sq = x.x * x.x + x.y * x.y + x.z * x.z + x.w * x.w;
    s = warpSum(s);
    sq = warpSum(sq);
    float mu = s * (1.0f / HDIM);
    float var = sq * (1.0f / HDIM) - mu * mu;
    float inv = rsqrtf(var + 1e-5f);
    float4 g = *(const float4*)(gamma + lane * 4);
    float4 b = *(const float4*)(beta + lane * 4);
    float4 y;
    y.x = (x.x - mu) * inv * g.x + b.x;
    y.y = (x.y - mu) * inv * g.y + b.y;
    y.z = (x.z - mu) * inv * g.z + b.z;
    y.w = (x.w - mu) * inv * g.w + b.w;
    float4 w = *(const float4*)(gw + lane * 4);
    float gp = y.x * w.x + y.y * w.y + y.z * w.z + y.w * w.w;
    gp = warpSum(gp);
    float p = __expf(gp + gb[0]);
    int gr = gid[node];
    if (lane == 0) atomicAdd(&d_gz[gr], p);
    redAdd4(d_zg + gr * HDIM + lane * 4, p * y.x, p * y.y, p * y.z, p * y.w);
}

// out = relu((zg/gz) @ W1 + b1) @ W2 + b2, one block per graph
__global__ void final_k(const float* __restrict__ W1, const float* __restrict__ b1,
                        const float* __restrict__ W2, const float* __restrict__ b2,
                        float* __restrict__ out) {
    __shared__ float row[HDIM];
    __shared__ float z1[HDIM];
    int g = blockIdx.x;
    int t = threadIdx.x;
    float gz = d_gz[g];
    float inv = (gz > 0.0f) ? (1.0f / gz) : 0.0f;
    row[t] = d_zg[g * HDIM + t] * inv;
    __syncthreads();
    float acc = b1[t];
    #pragma unroll 8
    for (int k = 0; k < HDIM; k++) acc += row[k] * W1[k * HDIM + t];
    z1[t] = (acc > 0.0f) ? acc : 0.0f;
    __syncthreads();
    if (t < 64) {
        float a2 = b2[t];
        #pragma unroll 8
        for (int k = 0; k < HDIM; k++) a2 += z1[k] * W2[k * 64 + t];
        out[g * 64 + t] = a2;
    }
}

// ---------------- launch ----------------
extern "C" void kernel_launch(void* const* d_in, const int* in_sizes, int n_in,
                              void* d_out, int out_size) {
    const int*   gt    = (const int*)d_in[0];
    const int*   qi    = (const int*)d_in[1];
    const int*   src   = (const int*)d_in[2];
    const int*   dst   = (const int*)d_in[3];
    const int*   gid   = (const int*)d_in[4];
    const float* ge    = (const float*)d_in[5];
    const float* qe    = (const float*)d_in[6];
    const float* W     = (const float*)d_in[7];
    const float* al    = (const float*)d_in[8];
    const float* ar    = (const float*)d_in[9];
    const float* bias  = (const float*)d_in[10];
    const float* gamma = (const float*)d_in[11];
    const float* beta  = (const float*)d_in[12];
    const float* gw    = (const float*)d_in[13];
    const float* gb    = (const float*)d_in[14];
    const float* W1    = (const float*)d_in[15];
    const float* b1    = (const float*)d_in[16];
    const float* W2    = (const float*)d_in[17];
    const float* b2    = (const float*)d_in[18];

    int n = in_sizes[0];
    int e = in_sizes[2];

    const int T = 256;
    int gGemm  = (n + 127) / 128;
    int gWarpN = (n * 32 + T - 1) / T;
    int gEdge  = (e + T - 1) / T;
    int gNode  = (n + T - 1) / T;
    int nb     = (n + 1023) / 1024;

    csr_zero_k<<<gNode, T>>>(n);                                   // 1
    csr_hist_k<<<gEdge, T>>>(dst, e);                              // 2
    csr_scan1_k<<<nb, 1024>>>(n);                                  // 3
    gemm_attn_k<<<gGemm, 256>>>(W, al, ar, n, 0, gt, qi, ge, qe);  // 4 (profiled)
    csr_scan2_k<<<1, 32>>>(nb, n);                                 // 5
    csr_scan3_k<<<nb, 1024>>>(n);                                  // 6
    csr_scatter_k<<<gEdge, T>>>(src, dst, e);                      // 7
    gat_fused_k<<<gWarpN, T>>>(bias, n, 0);                        // 8

    for (int l = 1; l < 3; l++) {
        gemm_attn_k<<<gGemm, 256>>>(W + l * HDIM * HDIM, al + l * HDIM, ar + l * HDIM,
                                    n, l, nullptr, nullptr, nullptr, nullptr);
        gat_fused_k<<<gWarpN, T>>>(bias + l * HDIM, n, l);
    }

    ln_gate_pool_k<<<gWarpN, T>>>(gamma, beta, gw, gb, gid, n);
    final_k<<<GMAX, HDIM>>>(W1, b1, W2, b2, (float*)d_out);
}